// round 15
// baseline (speedup 1.0000x reference)
#include <cuda_runtime.h>

#define EPS 1e-8f
#define BN 4
#define CN 128
#define HN 256
#define WN 256
#define HW (HN*WN)       // 65536
#define NCH (BN*CN)      // 512
#define MHW (128*128)    // 16384
#define NPART 4

// Scratch: per-channel partial sums (NPART parts) + final coefficients.
__device__ float g_sums[NPART * NCH * 12];
__device__ float g_coef[NCH * 4];          // per channel: P, Q, k1, k2

__device__ __forceinline__ float warpSum(float v) {
#pragma unroll
    for (int o = 16; o; o >>= 1) v += __shfl_xor_sync(0xffffffffu, v, o);
    return v;
}

__device__ __forceinline__ void gdc_wait() {
    asm volatile("griddepcontrol.wait;" ::: "memory");
}
__device__ __forceinline__ void gdc_launch_dependents() {
    asm volatile("griddepcontrol.launch_dependents;" ::: "memory");
}

// ---------------------------------------------------------------------------
// Kernel 1: per-(b,c) partial reductions, split by tensor.
// BID MAP: x2 = bids 0..2047 (streamed, runs first); x1 = bids 2048..4095,
// batch-sequential. x1 batches 1..3 (100MB — fits 126MB L2 alongside
// evict-first transients) load with DEFAULT policy and survive into k_apply
// (which walks channels in reverse, reading b3->b1 as L2 hits). R13 proved
// the retention mechanism works at 67MB; R15 raises the dose to 100MB.
//   A = Sum x*m, B = Sum x*m^3, C = Sum x^2*m^4  per region;
// mask 2x2-upsample factoring: sx=sum4(x), sq=sum4(x^2) per mask scalar.
// ---------------------------------------------------------------------------
template<bool STREAM>
__device__ __forceinline__ void reduce_body(const float4* __restrict__ p,
                                            const float* __restrict__ mb,
                                            int part, int t, float* acc) {
    int col = t & 63;
    int rpl0 = t >> 6;
#pragma unroll 1
    for (int k = 0; k < 8; k++) {
        int rp = k * 4 + rpl0;
        int q0 = rp * 128 + col;
        float4 xa = STREAM ? __ldcs(p + q0) : p[q0];
        float4 xb = STREAM ? __ldcs(p + q0 + 64) : p[q0 + 64];
        int mrow = part * 32 + rp;
        float2 mp = *reinterpret_cast<const float2*>(mb + mrow * 128 + 2 * col);

#pragma unroll
        for (int hsel = 0; hsel < 2; hsel++) {
            float m = hsel ? mp.y : mp.x;
            float e0 = hsel ? xa.z : xa.x, e1 = hsel ? xa.w : xa.y;
            float e2 = hsel ? xb.z : xb.x, e3 = hsel ? xb.w : xb.y;

            float om = 1.0f - m;
            float m2 = m * m, om2 = om * om;

            float sx = (e0 + e1) + (e2 + e3);
            float sq = fmaf(e0, e0, fmaf(e1, e1, fmaf(e2, e2, e3 * e3)));
            acc[0] = fmaf(sx, m, acc[0]);
            acc[1] = fmaf(sx * m, m2, acc[1]);
            acc[2] = fmaf(sq, m2 * m2, acc[2]);
            acc[3] = fmaf(sx, om, acc[3]);
            acc[4] = fmaf(sx * om, om2, acc[4]);
            acc[5] = fmaf(sq, om2 * om2, acc[5]);
        }
    }
}

__global__ __launch_bounds__(256) void k_reduce(const float4* __restrict__ x1,
                                                const float4* __restrict__ x2,
                                                const float* __restrict__ mask) {
    int bid  = blockIdx.x;
    int tensor, ch, part, b;
    if (bid < 2048) {
        // x2 half: runs first, fully streamed. ch-major/part layout.
        tensor = 1;
        ch = bid & (NCH - 1);
        part = bid >> 9;
        b = ch >> 7;
    } else {
        // x1 half: batch-SEQUENTIAL so higher batches run later.
        tensor = 0;
        int idx = bid - 2048;          // 0..2047
        b = idx >> 9;                  // 0..3 sequential
        part = (idx >> 7) & (NPART - 1);
        int c = idx & (CN - 1);
        ch = b * CN + c;
    }
    const float4* p = (tensor ? x2 : x1) + (size_t)ch * (HW / 4) + part * 4096;
    const float*  mb = mask + b * MHW;
    int t = threadIdx.x;
    int lane = t & 31, wid = t >> 5;

    float acc[6];
#pragma unroll
    for (int i = 0; i < 6; i++) acc[i] = 0.f;

    // x1 batches 1-3 (100MB): default policy -> survive into k_apply.
    if (tensor == 0 && b >= 1) reduce_body<false>(p, mb, part, t, acc);
    else                       reduce_body<true >(p, mb, part, t, acc);

    __shared__ float red[6][8];
#pragma unroll
    for (int i = 0; i < 6; i++) {
        float s = warpSum(acc[i]);
        if (lane == 0) red[i][wid] = s;
    }
    __syncthreads();
    if (wid == 0) {
#pragma unroll
        for (int i = 0; i < 6; i++) {
            float s = (lane < 8) ? red[i][lane] : 0.f;
            s = warpSum(s);
            if (lane == 0)
                g_sums[(size_t)(part * NCH + ch) * 12 + tensor * 6 + i] = s;
        }
    }
    __threadfence();
    __syncthreads();
    gdc_launch_dependents();
}

// ---------------------------------------------------------------------------
// Kernel 2 (R12 measured-good, unchanged): stats + modulation GEMVs.
// grid (BN, 16): 64 blocks, each owns 8 channels. PRE-WAIT: weight rows ->
// smem + mask sums. POST-WAIT: combine g_sums, stats, smem GEMV, coefs.
//   out = x1*(m^2*P + om^2*Q) + k1*m + k2*om
// ---------------------------------------------------------------------------
__global__ __launch_bounds__(256) void k_small(const float* __restrict__ mask,
                                               const float* __restrict__ w_in_mean,
                                               const float* __restrict__ w_in_var,
                                               const float* __restrict__ w_out_mean,
                                               const float* __restrict__ w_out_var) {
    int b  = blockIdx.x;
    int rg = blockIdx.y;              // 8-row group: rows [rg*8, rg*8+8)
    int t = threadIdx.x;
    int lane = t & 31, wid = t >> 5;

    __shared__ float w_sh[4][8][256]; // 32KB: [mat][local_row][j]
    __shared__ float ssum[CN * 12];
    __shared__ float v_sh[4 * 256];
    __shared__ float ada_sh[32];
    __shared__ float sred[2][8];
    __shared__ float sh_nin, sh_nout, sh_M2, sh_M2o;

    // ---- PRE-WAIT: weight prefetch ----
    {
        const float* wmats[4] = {w_in_mean, w_in_var, w_out_mean, w_out_var};
#pragma unroll
        for (int it = 0; it < 8; it++) {
            int id = t + it * 256;
            int mat = id >> 9;
            int rem = id & 511;
            int row = rem >> 6;
            int j4  = rem & 63;
            reinterpret_cast<float4*>(&w_sh[mat][row][0])[j4] =
                reinterpret_cast<const float4*>(wmats[mat] + (size_t)(rg * 8 + row) * 256)[j4];
        }
    }

    // ---- PRE-WAIT: mask sums (exact: 2x2-repeat upsample) ----
    const float* mb = mask + b * MHW;
    {
        float s1 = 0, s2 = 0;
        for (int i = t; i < MHW; i += 256) { float m = mb[i]; s1 += m; s2 += m * m; }
        s1 = warpSum(s1); s2 = warpSum(s2);
        if (lane == 0) { sred[0][wid] = s1; sred[1][wid] = s2; }
    }
    __syncthreads();
    if (t == 0) {
        float S1 = 0, S2 = 0;
        for (int i = 0; i < 8; i++) { S1 += sred[0][i]; S2 += sred[1][i]; }
        float msum = 4.f * S1, m2sum = 4.f * S2;
        sh_nin  = msum + EPS;
        sh_nout = ((float)HW - msum) + EPS;
        sh_M2   = m2sum;
        sh_M2o  = (float)HW - 2.f * msum + m2sum;
    }

    gdc_wait();

    for (int id = t; id < CN * 12; id += 256) {
        int c = id / 12, i = id - c * 12;
        float v = 0.f;
#pragma unroll
        for (int p = 0; p < NPART; p++)
            v += g_sums[(size_t)(p * NCH + b * CN + c) * 12 + i];
        ssum[id] = v;
    }
    __syncthreads();

    {
        int c = t & 127;
        int isx2 = t >> 7;
        const float* s = ssum + c * 12 + isx2 * 6;
        float A = s[0], Bb = s[1], Cc = s[2], Ao = s[3], Bo = s[4], Co = s[5];
        float mean_in = A / sh_nin;
        float var_in = (Cc - 2.f * mean_in * Bb + mean_in * mean_in * sh_M2) / sh_nin;
        var_in = fmaxf(var_in, 0.f);
        float mean_out = Ao / sh_nout;
        float var_out = (Co - 2.f * mean_out * Bo + mean_out * mean_out * sh_M2o) / sh_nout;
        var_out = fmaxf(var_out, 0.f);
        int vi = isx2 * 128 + c;
        v_sh[vi]       = mean_in;
        v_sh[256 + vi] = var_in;
        v_sh[512 + vi] = mean_out;
        v_sh[768 + vi] = var_out;
    }
    __syncthreads();

    {
#pragma unroll
        for (int it = 0; it < 4; it++) {
            int task = wid * 4 + it;
            int mat = task >> 3, lr = task & 7;
            const float* wrow = &w_sh[mat][lr][0];
            const float* vv = v_sh + mat * 256;
            float a = 0.f;
#pragma unroll
            for (int j = 0; j < 8; j++)
                a = fmaf(wrow[lane + 32 * j], vv[lane + 32 * j], a);
            a = warpSum(a);
            if (lane == 0) ada_sh[task] = a;
        }
    }
    __syncthreads();

    if (t < 8) {
        int c = rg * 8 + t;
        float mu_i = v_sh[c],       r_i = rsqrtf(v_sh[256 + c] + EPS);
        float mu_o = v_sh[512 + c], r_o = rsqrtf(v_sh[768 + c] + EPS);
        float P  = r_i * ada_sh[8 + t];
        float Q  = r_o * ada_sh[24 + t];
        float k1 = ada_sh[t]      - mu_i * P;
        float k2 = ada_sh[16 + t] - mu_o * Q;
        reinterpret_cast<float4*>(g_coef)[b * CN + c] = make_float4(P, Q, k1, k2);
    }
    __threadfence();
    __syncthreads();
    gdc_launch_dependents();
}

// ---------------------------------------------------------------------------
// Kernel 3: elementwise apply, reverse channel walk (reads L2-resident x1
// batches 3->1 first). x1 reads __ldcs (line is dead after this read —
// demote it so remaining resident lines keep their ways); output stores
// __stcs (write traffic must not churn residency). PRE-WAIT: x1+mask loads.
// out = x1*(m^2*P + om^2*Q) + k1*m + k2*om
// ---------------------------------------------------------------------------
__global__ __launch_bounds__(256) void k_apply(const float4* __restrict__ x1,
                                               const float* __restrict__ mask,
                                               float4* __restrict__ out) {
    int ch = (NCH - 1) - blockIdx.y;             // reverse channel walk
    int b = ch >> 7;
    const float* mb = mask + b * MHW;
    const float4* px = x1 + (size_t)ch * (HW / 4);
    float4* po = out + (size_t)ch * (HW / 4);
    int q0 = blockIdx.x * 512 + threadIdx.x;

    // pre-wait independent loads (hits still hit under __ldcs; misses fill
    // evict-first, which is what we want for the b0 portion)
    float4 v0 = __ldcs(px + q0);
    float4 v1 = __ldcs(px + q0 + 256);
    int mi0 = ((q0 >> 7) << 7) | ((2 * q0) & 126);
    int q1 = q0 + 256;
    int mi1 = ((q1 >> 7) << 7) | ((2 * q1) & 126);
    float2 mp0 = *reinterpret_cast<const float2*>(mb + mi0);
    float2 mp1 = *reinterpret_cast<const float2*>(mb + mi1);

    gdc_wait();

    float4 coef = __ldg(&reinterpret_cast<const float4*>(g_coef)[ch]);
    float P = coef.x, Q = coef.y, k1 = coef.z, k2 = coef.w;

#pragma unroll
    for (int r = 0; r < 2; r++) {
        int q = r ? q1 : q0;
        float4 v = r ? v1 : v0;
        float2 mp = r ? mp1 : mp0;
        float xs[4] = {v.x, v.y, v.z, v.w};
        float ms[4] = {mp.x, mp.x, mp.y, mp.y};
        float os[4];
#pragma unroll
        for (int i = 0; i < 4; i++) {
            float m = ms[i], om = 1.f - m;
            float s = m * m * P + om * om * Q;
            os[i] = xs[i] * s + k1 * m + k2 * om;
        }
        __stcs(po + q, make_float4(os[0], os[1], os[2], os[3]));
    }
}

extern "C" void kernel_launch(void* const* d_in, const int* in_sizes, int n_in,
                              void* d_out, int out_size) {
    const float* x1         = (const float*)d_in[0];
    const float* x2         = (const float*)d_in[1];
    const float* mask       = (const float*)d_in[2];
    const float* w_in_mean  = (const float*)d_in[3];
    const float* w_in_var   = (const float*)d_in[4];
    const float* w_out_mean = (const float*)d_in[5];
    const float* w_out_var  = (const float*)d_in[6];
    float* out = (float*)d_out;

    // 1) reduce — plain launch, residency-ordered tensor-split grid
    k_reduce<<<2 * NPART * NCH, 256>>>((const float4*)x1, (const float4*)x2, mask);

    // 2) stats+gemv — PDL consumer of reduce
    {
        cudaLaunchConfig_t cfg = {};
        cfg.gridDim = dim3(BN, 16);
        cfg.blockDim = dim3(256);
        cudaLaunchAttribute attr[1];
        attr[0].id = cudaLaunchAttributeProgrammaticStreamSerialization;
        attr[0].val.programmaticStreamSerializationAllowed = 1;
        cfg.attrs = attr;
        cfg.numAttrs = 1;
        cudaLaunchKernelEx(&cfg, k_small, mask, w_in_mean, w_in_var, w_out_mean, w_out_var);
    }

    // 3) apply — PDL consumer of k_small
    {
        cudaLaunchConfig_t cfg = {};
        cfg.gridDim = dim3(HW / 4 / 512, NCH);
        cfg.blockDim = dim3(256);
        cudaLaunchAttribute attr[1];
        attr[0].id = cudaLaunchAttributeProgrammaticStreamSerialization;
        attr[0].val.programmaticStreamSerializationAllowed = 1;
        cfg.attrs = attr;
        cfg.numAttrs = 1;
        cudaLaunchKernelEx(&cfg, k_apply, (const float4*)x1, mask, (float4*)out);
    }
}

// round 16
// speedup vs baseline: 1.0178x; 1.0178x over previous
#include <cuda_runtime.h>

#define EPS 1e-8f
#define BN 4
#define CN 128
#define HN 256
#define WN 256
#define HW (HN*WN)       // 65536
#define NCH (BN*CN)      // 512
#define MHW (128*128)    // 16384
#define NPART 4

// Scratch: per-channel partial sums (NPART parts) + final coefficients.
__device__ float g_sums[NPART * NCH * 12];
__device__ float g_coef[NCH * 4];          // per channel: P, Q, k1, k2

__device__ __forceinline__ float warpSum(float v) {
#pragma unroll
    for (int o = 16; o; o >>= 1) v += __shfl_xor_sync(0xffffffffu, v, o);
    return v;
}

__device__ __forceinline__ void gdc_wait() {
    asm volatile("griddepcontrol.wait;" ::: "memory");
}
__device__ __forceinline__ void gdc_launch_dependents() {
    asm volatile("griddepcontrol.launch_dependents;" ::: "memory");
}

// ---------------------------------------------------------------------------
// Kernel 1 (R14 measured-good): per-(b,c) partial reductions, split by
// tensor. BID MAP: x2 = bids 0..2047 (streamed, runs first); x1 = bids
// 2048..4095, batch-sequential so x1 batches 2-3 are the FINAL 1024 bids.
// Those 67MB load with DEFAULT policy and survive L2 into k_apply (reverse
// walk reads them first). Dose-response mapped: 67MB=+2us, 100MB=-3.4us
// (R15 overshot) — 67MB is the operating point.
//   A = Sum x*m, B = Sum x*m^3, C = Sum x^2*m^4  per region;
// mask 2x2-upsample factoring: sx=sum4(x), sq=sum4(x^2) per mask scalar.
// ---------------------------------------------------------------------------
template<bool STREAM>
__device__ __forceinline__ void reduce_body(const float4* __restrict__ p,
                                            const float* __restrict__ mb,
                                            int part, int t, float* acc) {
    int col = t & 63;
    int rpl0 = t >> 6;
#pragma unroll 1
    for (int k = 0; k < 8; k++) {
        int rp = k * 4 + rpl0;
        int q0 = rp * 128 + col;
        float4 xa = STREAM ? __ldcs(p + q0) : p[q0];
        float4 xb = STREAM ? __ldcs(p + q0 + 64) : p[q0 + 64];
        int mrow = part * 32 + rp;
        float2 mp = *reinterpret_cast<const float2*>(mb + mrow * 128 + 2 * col);

#pragma unroll
        for (int hsel = 0; hsel < 2; hsel++) {
            float m = hsel ? mp.y : mp.x;
            float e0 = hsel ? xa.z : xa.x, e1 = hsel ? xa.w : xa.y;
            float e2 = hsel ? xb.z : xb.x, e3 = hsel ? xb.w : xb.y;

            float om = 1.0f - m;
            float m2 = m * m, om2 = om * om;

            float sx = (e0 + e1) + (e2 + e3);
            float sq = fmaf(e0, e0, fmaf(e1, e1, fmaf(e2, e2, e3 * e3)));
            acc[0] = fmaf(sx, m, acc[0]);
            acc[1] = fmaf(sx * m, m2, acc[1]);
            acc[2] = fmaf(sq, m2 * m2, acc[2]);
            acc[3] = fmaf(sx, om, acc[3]);
            acc[4] = fmaf(sx * om, om2, acc[4]);
            acc[5] = fmaf(sq, om2 * om2, acc[5]);
        }
    }
}

__global__ __launch_bounds__(256) void k_reduce(const float4* __restrict__ x1,
                                                const float4* __restrict__ x2,
                                                const float* __restrict__ mask) {
    int bid  = blockIdx.x;
    int tensor, ch, part, b;
    if (bid < 2048) {
        // x2 half: runs first, fully streamed. ch-major/part layout.
        tensor = 1;
        ch = bid & (NCH - 1);
        part = bid >> 9;
        b = ch >> 7;
    } else {
        // x1 half: batch-SEQUENTIAL so batches 2-3 are the last 1024 bids.
        tensor = 0;
        int idx = bid - 2048;          // 0..2047
        b = idx >> 9;                  // 0..3 sequential
        part = (idx >> 7) & (NPART - 1);
        int c = idx & (CN - 1);
        ch = b * CN + c;
    }
    const float4* p = (tensor ? x2 : x1) + (size_t)ch * (HW / 4) + part * 4096;
    const float*  mb = mask + b * MHW;
    int t = threadIdx.x;
    int lane = t & 31, wid = t >> 5;

    float acc[6];
#pragma unroll
    for (int i = 0; i < 6; i++) acc[i] = 0.f;

    // x1 batches 2-3 (67MB, final bids): default policy -> survive to apply.
    if (tensor == 0 && b >= 2) reduce_body<false>(p, mb, part, t, acc);
    else                       reduce_body<true >(p, mb, part, t, acc);

    __shared__ float red[6][8];
#pragma unroll
    for (int i = 0; i < 6; i++) {
        float s = warpSum(acc[i]);
        if (lane == 0) red[i][wid] = s;
    }
    __syncthreads();
    if (wid == 0) {
#pragma unroll
        for (int i = 0; i < 6; i++) {
            float s = (lane < 8) ? red[i][lane] : 0.f;
            s = warpSum(s);
            if (lane == 0)
                g_sums[(size_t)(part * NCH + ch) * 12 + tensor * 6 + i] = s;
        }
    }
    __threadfence();
    __syncthreads();
    gdc_launch_dependents();
}

// ---------------------------------------------------------------------------
// Kernel 2 (R12 measured-good, unchanged): stats + modulation GEMVs.
// grid (BN, 16): 64 blocks, each owns 8 channels. PRE-WAIT: weight rows ->
// smem + mask sums. POST-WAIT: combine g_sums, stats, smem GEMV, coefs.
//   out = x1*(m^2*P + om^2*Q) + k1*m + k2*om
// ---------------------------------------------------------------------------
__global__ __launch_bounds__(256) void k_small(const float* __restrict__ mask,
                                               const float* __restrict__ w_in_mean,
                                               const float* __restrict__ w_in_var,
                                               const float* __restrict__ w_out_mean,
                                               const float* __restrict__ w_out_var) {
    int b  = blockIdx.x;
    int rg = blockIdx.y;              // 8-row group: rows [rg*8, rg*8+8)
    int t = threadIdx.x;
    int lane = t & 31, wid = t >> 5;

    __shared__ float w_sh[4][8][256]; // 32KB: [mat][local_row][j]
    __shared__ float ssum[CN * 12];
    __shared__ float v_sh[4 * 256];
    __shared__ float ada_sh[32];
    __shared__ float sred[2][8];
    __shared__ float sh_nin, sh_nout, sh_M2, sh_M2o;

    // ---- PRE-WAIT: weight prefetch ----
    {
        const float* wmats[4] = {w_in_mean, w_in_var, w_out_mean, w_out_var};
#pragma unroll
        for (int it = 0; it < 8; it++) {
            int id = t + it * 256;
            int mat = id >> 9;
            int rem = id & 511;
            int row = rem >> 6;
            int j4  = rem & 63;
            reinterpret_cast<float4*>(&w_sh[mat][row][0])[j4] =
                reinterpret_cast<const float4*>(wmats[mat] + (size_t)(rg * 8 + row) * 256)[j4];
        }
    }

    // ---- PRE-WAIT: mask sums (exact: 2x2-repeat upsample) ----
    const float* mb = mask + b * MHW;
    {
        float s1 = 0, s2 = 0;
        for (int i = t; i < MHW; i += 256) { float m = mb[i]; s1 += m; s2 += m * m; }
        s1 = warpSum(s1); s2 = warpSum(s2);
        if (lane == 0) { sred[0][wid] = s1; sred[1][wid] = s2; }
    }
    __syncthreads();
    if (t == 0) {
        float S1 = 0, S2 = 0;
        for (int i = 0; i < 8; i++) { S1 += sred[0][i]; S2 += sred[1][i]; }
        float msum = 4.f * S1, m2sum = 4.f * S2;
        sh_nin  = msum + EPS;
        sh_nout = ((float)HW - msum) + EPS;
        sh_M2   = m2sum;
        sh_M2o  = (float)HW - 2.f * msum + m2sum;
    }

    gdc_wait();

    for (int id = t; id < CN * 12; id += 256) {
        int c = id / 12, i = id - c * 12;
        float v = 0.f;
#pragma unroll
        for (int p = 0; p < NPART; p++)
            v += g_sums[(size_t)(p * NCH + b * CN + c) * 12 + i];
        ssum[id] = v;
    }
    __syncthreads();

    {
        int c = t & 127;
        int isx2 = t >> 7;
        const float* s = ssum + c * 12 + isx2 * 6;
        float A = s[0], Bb = s[1], Cc = s[2], Ao = s[3], Bo = s[4], Co = s[5];
        float mean_in = A / sh_nin;
        float var_in = (Cc - 2.f * mean_in * Bb + mean_in * mean_in * sh_M2) / sh_nin;
        var_in = fmaxf(var_in, 0.f);
        float mean_out = Ao / sh_nout;
        float var_out = (Co - 2.f * mean_out * Bo + mean_out * mean_out * sh_M2o) / sh_nout;
        var_out = fmaxf(var_out, 0.f);
        int vi = isx2 * 128 + c;
        v_sh[vi]       = mean_in;
        v_sh[256 + vi] = var_in;
        v_sh[512 + vi] = mean_out;
        v_sh[768 + vi] = var_out;
    }
    __syncthreads();

    {
#pragma unroll
        for (int it = 0; it < 4; it++) {
            int task = wid * 4 + it;
            int mat = task >> 3, lr = task & 7;
            const float* wrow = &w_sh[mat][lr][0];
            const float* vv = v_sh + mat * 256;
            float a = 0.f;
#pragma unroll
            for (int j = 0; j < 8; j++)
                a = fmaf(wrow[lane + 32 * j], vv[lane + 32 * j], a);
            a = warpSum(a);
            if (lane == 0) ada_sh[task] = a;
        }
    }
    __syncthreads();

    if (t < 8) {
        int c = rg * 8 + t;
        float mu_i = v_sh[c],       r_i = rsqrtf(v_sh[256 + c] + EPS);
        float mu_o = v_sh[512 + c], r_o = rsqrtf(v_sh[768 + c] + EPS);
        float P  = r_i * ada_sh[8 + t];
        float Q  = r_o * ada_sh[24 + t];
        float k1 = ada_sh[t]      - mu_i * P;
        float k2 = ada_sh[16 + t] - mu_o * Q;
        reinterpret_cast<float4*>(g_coef)[b * CN + c] = make_float4(P, Q, k1, k2);
    }
    __threadfence();
    __syncthreads();
    gdc_launch_dependents();
}

// ---------------------------------------------------------------------------
// Kernel 3: elementwise apply, reverse channel walk (reads L2-resident x1
// batches 3->2 first). x1 reads __ldcs: hits still hit, and the consumed
// line is demoted (dead after this read) so remaining resident lines keep
// their ways; misses fill evict-first. __stcs output stores. PRE-WAIT:
// x1 + mask loads.   out = x1*(m^2*P + om^2*Q) + k1*m + k2*om
// ---------------------------------------------------------------------------
__global__ __launch_bounds__(256) void k_apply(const float4* __restrict__ x1,
                                               const float* __restrict__ mask,
                                               float4* __restrict__ out) {
    int ch = (NCH - 1) - blockIdx.y;             // reverse channel walk
    int b = ch >> 7;
    const float* mb = mask + b * MHW;
    const float4* px = x1 + (size_t)ch * (HW / 4);
    float4* po = out + (size_t)ch * (HW / 4);
    int q0 = blockIdx.x * 512 + threadIdx.x;

    // pre-wait independent loads
    float4 v0 = __ldcs(px + q0);
    float4 v1 = __ldcs(px + q0 + 256);
    int mi0 = ((q0 >> 7) << 7) | ((2 * q0) & 126);
    int q1 = q0 + 256;
    int mi1 = ((q1 >> 7) << 7) | ((2 * q1) & 126);
    float2 mp0 = *reinterpret_cast<const float2*>(mb + mi0);
    float2 mp1 = *reinterpret_cast<const float2*>(mb + mi1);

    gdc_wait();

    float4 coef = __ldg(&reinterpret_cast<const float4*>(g_coef)[ch]);
    float P = coef.x, Q = coef.y, k1 = coef.z, k2 = coef.w;

#pragma unroll
    for (int r = 0; r < 2; r++) {
        int q = r ? q1 : q0;
        float4 v = r ? v1 : v0;
        float2 mp = r ? mp1 : mp0;
        float xs[4] = {v.x, v.y, v.z, v.w};
        float ms[4] = {mp.x, mp.x, mp.y, mp.y};
        float os[4];
#pragma unroll
        for (int i = 0; i < 4; i++) {
            float m = ms[i], om = 1.f - m;
            float s = m * m * P + om * om * Q;
            os[i] = xs[i] * s + k1 * m + k2 * om;
        }
        __stcs(po + q, make_float4(os[0], os[1], os[2], os[3]));
    }
}

extern "C" void kernel_launch(void* const* d_in, const int* in_sizes, int n_in,
                              void* d_out, int out_size) {
    const float* x1         = (const float*)d_in[0];
    const float* x2         = (const float*)d_in[1];
    const float* mask       = (const float*)d_in[2];
    const float* w_in_mean  = (const float*)d_in[3];
    const float* w_in_var   = (const float*)d_in[4];
    const float* w_out_mean = (const float*)d_in[5];
    const float* w_out_var  = (const float*)d_in[6];
    float* out = (float*)d_out;

    // 1) reduce — plain launch, residency-ordered tensor-split grid
    k_reduce<<<2 * NPART * NCH, 256>>>((const float4*)x1, (const float4*)x2, mask);

    // 2) stats+gemv — PDL consumer of reduce
    {
        cudaLaunchConfig_t cfg = {};
        cfg.gridDim = dim3(BN, 16);
        cfg.blockDim = dim3(256);
        cudaLaunchAttribute attr[1];
        attr[0].id = cudaLaunchAttributeProgrammaticStreamSerialization;
        attr[0].val.programmaticStreamSerializationAllowed = 1;
        cfg.attrs = attr;
        cfg.numAttrs = 1;
        cudaLaunchKernelEx(&cfg, k_small, mask, w_in_mean, w_in_var, w_out_mean, w_out_var);
    }

    // 3) apply — PDL consumer of k_small
    {
        cudaLaunchConfig_t cfg = {};
        cfg.gridDim = dim3(HW / 4 / 512, NCH);
        cfg.blockDim = dim3(256);
        cudaLaunchAttribute attr[1];
        attr[0].id = cudaLaunchAttributeProgrammaticStreamSerialization;
        attr[0].val.programmaticStreamSerializationAllowed = 1;
        cfg.attrs = attr;
        cfg.numAttrs = 1;
        cudaLaunchKernelEx(&cfg, k_apply, (const float4*)x1, mask, (float4*)out);
    }
}

// round 17
// speedup vs baseline: 1.0388x; 1.0207x over previous
#include <cuda_runtime.h>

#define EPS 1e-8f
#define BN 4
#define CN 128
#define HN 256
#define WN 256
#define HW (HN*WN)       // 65536
#define NCH (BN*CN)      // 512
#define MHW (128*128)    // 16384
#define NPART 4

// Scratch: per-channel partial sums (NPART parts) + final coefficients.
__device__ float g_sums[NPART * NCH * 12];
__device__ float g_coef[NCH * 4];          // per channel: P, Q, k1, k2

__device__ __forceinline__ float warpSum(float v) {
#pragma unroll
    for (int o = 16; o; o >>= 1) v += __shfl_xor_sync(0xffffffffu, v, o);
    return v;
}

__device__ __forceinline__ void gdc_wait() {
    asm volatile("griddepcontrol.wait;" ::: "memory");
}
__device__ __forceinline__ void gdc_launch_dependents() {
    asm volatile("griddepcontrol.launch_dependents;" ::: "memory");
}

// ---------------------------------------------------------------------------
// FINAL FORM (== R14, the measured-best 88.35us configuration).
//
// Kernel 1: per-(b,c) partial reductions, split by tensor.
// BID MAP: x2 = bids 0..2047 (streamed, runs first); x1 = bids 2048..4095,
// batch-sequential so x1 batches 2-3 are the FINAL 1024 bids. Those 67MB
// load with DEFAULT policy and survive L2 into k_apply (reverse walk reads
// them first). Dose-response mapped across the session:
//   0MB -> apply 36.4us | 67MB -> 34.4us (optimum) | 100MB -> ~37us
// Apply-read policy: default beats __ldcs (R16: -1.7us for __ldcs).
//   A = Sum x*m, B = Sum x*m^3, C = Sum x^2*m^4  per region;
// mask 2x2-upsample factoring: sx=sum4(x), sq=sum4(x^2) per mask scalar.
// ---------------------------------------------------------------------------
template<bool STREAM>
__device__ __forceinline__ void reduce_body(const float4* __restrict__ p,
                                            const float* __restrict__ mb,
                                            int part, int t, float* acc) {
    int col = t & 63;
    int rpl0 = t >> 6;
#pragma unroll 1
    for (int k = 0; k < 8; k++) {
        int rp = k * 4 + rpl0;
        int q0 = rp * 128 + col;
        float4 xa = STREAM ? __ldcs(p + q0) : p[q0];
        float4 xb = STREAM ? __ldcs(p + q0 + 64) : p[q0 + 64];
        int mrow = part * 32 + rp;
        float2 mp = *reinterpret_cast<const float2*>(mb + mrow * 128 + 2 * col);

#pragma unroll
        for (int hsel = 0; hsel < 2; hsel++) {
            float m = hsel ? mp.y : mp.x;
            float e0 = hsel ? xa.z : xa.x, e1 = hsel ? xa.w : xa.y;
            float e2 = hsel ? xb.z : xb.x, e3 = hsel ? xb.w : xb.y;

            float om = 1.0f - m;
            float m2 = m * m, om2 = om * om;

            float sx = (e0 + e1) + (e2 + e3);
            float sq = fmaf(e0, e0, fmaf(e1, e1, fmaf(e2, e2, e3 * e3)));
            acc[0] = fmaf(sx, m, acc[0]);
            acc[1] = fmaf(sx * m, m2, acc[1]);
            acc[2] = fmaf(sq, m2 * m2, acc[2]);
            acc[3] = fmaf(sx, om, acc[3]);
            acc[4] = fmaf(sx * om, om2, acc[4]);
            acc[5] = fmaf(sq, om2 * om2, acc[5]);
        }
    }
}

__global__ __launch_bounds__(256) void k_reduce(const float4* __restrict__ x1,
                                                const float4* __restrict__ x2,
                                                const float* __restrict__ mask) {
    int bid  = blockIdx.x;
    int tensor, ch, part, b;
    if (bid < 2048) {
        // x2 half: runs first, fully streamed. ch-major/part layout.
        tensor = 1;
        ch = bid & (NCH - 1);
        part = bid >> 9;
        b = ch >> 7;
    } else {
        // x1 half: batch-SEQUENTIAL so batches 2-3 are the last 1024 bids.
        tensor = 0;
        int idx = bid - 2048;          // 0..2047
        b = idx >> 9;                  // 0..3 sequential
        part = (idx >> 7) & (NPART - 1);
        int c = idx & (CN - 1);
        ch = b * CN + c;
    }
    const float4* p = (tensor ? x2 : x1) + (size_t)ch * (HW / 4) + part * 4096;
    const float*  mb = mask + b * MHW;
    int t = threadIdx.x;
    int lane = t & 31, wid = t >> 5;

    float acc[6];
#pragma unroll
    for (int i = 0; i < 6; i++) acc[i] = 0.f;

    // x1 batches 2-3 (67MB, final bids): default policy -> survive to apply.
    if (tensor == 0 && b >= 2) reduce_body<false>(p, mb, part, t, acc);
    else                       reduce_body<true >(p, mb, part, t, acc);

    __shared__ float red[6][8];
#pragma unroll
    for (int i = 0; i < 6; i++) {
        float s = warpSum(acc[i]);
        if (lane == 0) red[i][wid] = s;
    }
    __syncthreads();
    if (wid == 0) {
#pragma unroll
        for (int i = 0; i < 6; i++) {
            float s = (lane < 8) ? red[i][lane] : 0.f;
            s = warpSum(s);
            if (lane == 0)
                g_sums[(size_t)(part * NCH + ch) * 12 + tensor * 6 + i] = s;
        }
    }
    __threadfence();
    __syncthreads();
    gdc_launch_dependents();
}

// ---------------------------------------------------------------------------
// Kernel 2: stats + modulation GEMVs. grid (BN, 16): 64 blocks, each owns
// 8 channels. PRE-WAIT (off critical path): weight rows -> smem (32KB) +
// per-batch mask sums. POST-WAIT (short): combine g_sums, per-channel
// stats, smem-resident GEMV, coefficients:
//   out = x1*(m^2*P + om^2*Q) + k1*m + k2*om
// ---------------------------------------------------------------------------
__global__ __launch_bounds__(256) void k_small(const float* __restrict__ mask,
                                               const float* __restrict__ w_in_mean,
                                               const float* __restrict__ w_in_var,
                                               const float* __restrict__ w_out_mean,
                                               const float* __restrict__ w_out_var) {
    int b  = blockIdx.x;
    int rg = blockIdx.y;              // 8-row group: rows [rg*8, rg*8+8)
    int t = threadIdx.x;
    int lane = t & 31, wid = t >> 5;

    __shared__ float w_sh[4][8][256]; // 32KB: [mat][local_row][j]
    __shared__ float ssum[CN * 12];
    __shared__ float v_sh[4 * 256];
    __shared__ float ada_sh[32];
    __shared__ float sred[2][8];
    __shared__ float sh_nin, sh_nout, sh_M2, sh_M2o;

    // ---- PRE-WAIT: weight prefetch ----
    {
        const float* wmats[4] = {w_in_mean, w_in_var, w_out_mean, w_out_var};
#pragma unroll
        for (int it = 0; it < 8; it++) {
            int id = t + it * 256;
            int mat = id >> 9;
            int rem = id & 511;
            int row = rem >> 6;
            int j4  = rem & 63;
            reinterpret_cast<float4*>(&w_sh[mat][row][0])[j4] =
                reinterpret_cast<const float4*>(wmats[mat] + (size_t)(rg * 8 + row) * 256)[j4];
        }
    }

    // ---- PRE-WAIT: mask sums (exact: 2x2-repeat upsample) ----
    const float* mb = mask + b * MHW;
    {
        float s1 = 0, s2 = 0;
        for (int i = t; i < MHW; i += 256) { float m = mb[i]; s1 += m; s2 += m * m; }
        s1 = warpSum(s1); s2 = warpSum(s2);
        if (lane == 0) { sred[0][wid] = s1; sred[1][wid] = s2; }
    }
    __syncthreads();
    if (t == 0) {
        float S1 = 0, S2 = 0;
        for (int i = 0; i < 8; i++) { S1 += sred[0][i]; S2 += sred[1][i]; }
        float msum = 4.f * S1, m2sum = 4.f * S2;
        sh_nin  = msum + EPS;
        sh_nout = ((float)HW - msum) + EPS;
        sh_M2   = m2sum;
        sh_M2o  = (float)HW - 2.f * msum + m2sum;
    }

    gdc_wait();

    for (int id = t; id < CN * 12; id += 256) {
        int c = id / 12, i = id - c * 12;
        float v = 0.f;
#pragma unroll
        for (int p = 0; p < NPART; p++)
            v += g_sums[(size_t)(p * NCH + b * CN + c) * 12 + i];
        ssum[id] = v;
    }
    __syncthreads();

    {
        int c = t & 127;
        int isx2 = t >> 7;
        const float* s = ssum + c * 12 + isx2 * 6;
        float A = s[0], Bb = s[1], Cc = s[2], Ao = s[3], Bo = s[4], Co = s[5];
        float mean_in = A / sh_nin;
        float var_in = (Cc - 2.f * mean_in * Bb + mean_in * mean_in * sh_M2) / sh_nin;
        var_in = fmaxf(var_in, 0.f);
        float mean_out = Ao / sh_nout;
        float var_out = (Co - 2.f * mean_out * Bo + mean_out * mean_out * sh_M2o) / sh_nout;
        var_out = fmaxf(var_out, 0.f);
        int vi = isx2 * 128 + c;
        v_sh[vi]       = mean_in;
        v_sh[256 + vi] = var_in;
        v_sh[512 + vi] = mean_out;
        v_sh[768 + vi] = var_out;
    }
    __syncthreads();

    {
#pragma unroll
        for (int it = 0; it < 4; it++) {
            int task = wid * 4 + it;
            int mat = task >> 3, lr = task & 7;
            const float* wrow = &w_sh[mat][lr][0];
            const float* vv = v_sh + mat * 256;
            float a = 0.f;
#pragma unroll
            for (int j = 0; j < 8; j++)
                a = fmaf(wrow[lane + 32 * j], vv[lane + 32 * j], a);
            a = warpSum(a);
            if (lane == 0) ada_sh[task] = a;
        }
    }
    __syncthreads();

    if (t < 8) {
        int c = rg * 8 + t;
        float mu_i = v_sh[c],       r_i = rsqrtf(v_sh[256 + c] + EPS);
        float mu_o = v_sh[512 + c], r_o = rsqrtf(v_sh[768 + c] + EPS);
        float P  = r_i * ada_sh[8 + t];
        float Q  = r_o * ada_sh[24 + t];
        float k1 = ada_sh[t]      - mu_i * P;
        float k2 = ada_sh[16 + t] - mu_o * Q;
        reinterpret_cast<float4*>(g_coef)[b * CN + c] = make_float4(P, Q, k1, k2);
    }
    __threadfence();
    __syncthreads();
    gdc_launch_dependents();
}

// ---------------------------------------------------------------------------
// Kernel 3: elementwise apply, reverse channel walk (reads the L2-resident
// x1 batches 3->2 first). x1 reads DEFAULT policy (hits must stay cheap —
// __ldcs reads measured -1.7us in R16); __stcs output stores (write traffic
// must not churn residency). PRE-WAIT: x1 + mask loads.
// out = x1*(m^2*P + om^2*Q) + k1*m + k2*om
// ---------------------------------------------------------------------------
__global__ __launch_bounds__(256) void k_apply(const float4* __restrict__ x1,
                                               const float* __restrict__ mask,
                                               float4* __restrict__ out) {
    int ch = (NCH - 1) - blockIdx.y;             // reverse channel walk
    int b = ch >> 7;
    const float* mb = mask + b * MHW;
    const float4* px = x1 + (size_t)ch * (HW / 4);
    float4* po = out + (size_t)ch * (HW / 4);
    int q0 = blockIdx.x * 512 + threadIdx.x;

    // pre-wait independent loads
    float4 v0 = px[q0];
    float4 v1 = px[q0 + 256];
    int mi0 = ((q0 >> 7) << 7) | ((2 * q0) & 126);
    int q1 = q0 + 256;
    int mi1 = ((q1 >> 7) << 7) | ((2 * q1) & 126);
    float2 mp0 = *reinterpret_cast<const float2*>(mb + mi0);
    float2 mp1 = *reinterpret_cast<const float2*>(mb + mi1);

    gdc_wait();

    float4 coef = __ldg(&reinterpret_cast<const float4*>(g_coef)[ch]);
    float P = coef.x, Q = coef.y, k1 = coef.z, k2 = coef.w;

#pragma unroll
    for (int r = 0; r < 2; r++) {
        int q = r ? q1 : q0;
        float4 v = r ? v1 : v0;
        float2 mp = r ? mp1 : mp0;
        float xs[4] = {v.x, v.y, v.z, v.w};
        float ms[4] = {mp.x, mp.x, mp.y, mp.y};
        float os[4];
#pragma unroll
        for (int i = 0; i < 4; i++) {
            float m = ms[i], om = 1.f - m;
            float s = m * m * P + om * om * Q;
            os[i] = xs[i] * s + k1 * m + k2 * om;
        }
        __stcs(po + q, make_float4(os[0], os[1], os[2], os[3]));
    }
}

extern "C" void kernel_launch(void* const* d_in, const int* in_sizes, int n_in,
                              void* d_out, int out_size) {
    const float* x1         = (const float*)d_in[0];
    const float* x2         = (const float*)d_in[1];
    const float* mask       = (const float*)d_in[2];
    const float* w_in_mean  = (const float*)d_in[3];
    const float* w_in_var   = (const float*)d_in[4];
    const float* w_out_mean = (const float*)d_in[5];
    const float* w_out_var  = (const float*)d_in[6];
    float* out = (float*)d_out;

    // 1) reduce — plain launch, residency-ordered tensor-split grid
    k_reduce<<<2 * NPART * NCH, 256>>>((const float4*)x1, (const float4*)x2, mask);

    // 2) stats+gemv — PDL consumer of reduce
    {
        cudaLaunchConfig_t cfg = {};
        cfg.gridDim = dim3(BN, 16);
        cfg.blockDim = dim3(256);
        cudaLaunchAttribute attr[1];
        attr[0].id = cudaLaunchAttributeProgrammaticStreamSerialization;
        attr[0].val.programmaticStreamSerializationAllowed = 1;
        cfg.attrs = attr;
        cfg.numAttrs = 1;
        cudaLaunchKernelEx(&cfg, k_small, mask, w_in_mean, w_in_var, w_out_mean, w_out_var);
    }

    // 3) apply — PDL consumer of k_small
    {
        cudaLaunchConfig_t cfg = {};
        cfg.gridDim = dim3(HW / 4 / 512, NCH);
        cfg.blockDim = dim3(256);
        cudaLaunchAttribute attr[1];
        attr[0].id = cudaLaunchAttributeProgrammaticStreamSerialization;
        attr[0].val.programmaticStreamSerializationAllowed = 1;
        cfg.attrs = attr;
        cfg.numAttrs = 1;
        cudaLaunchKernelEx(&cfg, k_apply, (const float4*)x1, mask, (float4*)out);
    }
}